// round 7
// baseline (speedup 1.0000x reference)
#include <cuda_runtime.h>

// DAG fused 1x1-conv, fp32, f32x2 FMA. 64-pos tiles, 2 blocks/SM.
// Block = (batch, 64-position tile), 128 threads, thread tile 8o x 4p.
// 5 state slots in smem (s0,s1,n0,n1,n2; relu'd) — node3 never consumed,
// goes straight to global. x0/x1 staged into the n1/n2 slots (free until
// their fin points). Weights [g][c][o] double-buffered in smem, unsplatted;
// {w,w} pairs via mov.b64. FMA order grouped by x operand for .reuse.

#define NG        16
#define NTHREADS  128
#define TPOS      64
#define SLOT      4096                       // floats per slot (64 c x 64 p)
#define SMEM_FLOATS (5 * SLOT + 2 * 4096)    // 5 states + 2 weight buffers
#define SMEM_BYTES  (SMEM_FLOATS * 4)        // 114688 B = 112 KB

// Schedule. Slots: 0=s0 1=s1 2=n0 3=n1 4=n2. x0 staged in slot3, x1 in
// slot4 (consumed at g0/g1, overwritten at fins g6/g10).
// c_fins: -1 none; 0..4 relu->slot (2..4 also raw->global node slot-2);
//          5 = node3, raw->global only.
__constant__ int c_in[NG]    = {3,4, 0,1, 0,1,2, 0,1,2,3, 0,1,2,3,4};
__constant__ int c_start[NG] = {1,1, 1,0, 1,0,0, 1,0,0,0, 1,0,0,0,0};
__constant__ int c_fins[NG]  = {0,1, -1,2, -1,-1,3, -1,-1,-1,4, -1,-1,-1,-1,5};

// [g][c][o] transposed weights
__device__ __align__(16) float g_wsp[NG * 4096];

__global__ void prep_weights_kernel(const float* __restrict__ Wpre,
                                    const float* __restrict__ Wedge) {
    int idx = blockIdx.x * blockDim.x + threadIdx.x;
    if (idx >= NG * 4096) return;
    int g = idx >> 12;
    int r = idx & 4095;
    int o = r >> 6;
    int c = r & 63;
    float w = (g < 2) ? Wpre[g * 4096 + o * 64 + c]
                      : Wedge[(g - 2) * 4096 + o * 64 + c];
    g_wsp[(g * 64 + c) * 64 + o] = w;
}

__device__ __forceinline__ void ffma2(unsigned long long& d,
                                      unsigned long long a,
                                      unsigned long long b) {
    asm("fma.rn.f32x2 %0, %1, %2, %0;" : "+l"(d) : "l"(a), "l"(b));
}
__device__ __forceinline__ unsigned long long splat2(float w) {
    unsigned long long r;
    asm("mov.b64 %0, {%1, %1};" : "=l"(r) : "f"(w));
    return r;
}
__device__ __forceinline__ float2 u2f2(unsigned long long v) {
    float2 r;
    asm("mov.b64 {%0, %1}, %2;" : "=f"(r.x), "=f"(r.y) : "l"(v));
    return r;
}

__global__ void __launch_bounds__(NTHREADS, 2)
dag_kernel(const float* __restrict__ x0,
           const float* __restrict__ x1,
           float* __restrict__ out) {
    extern __shared__ __align__(16) float sm[];
    float* st = sm;                 // 5 state slots [64 c][64 p]
    float* wb = sm + 5 * SLOT;      // 2 weight buffers [64 c][64 o]

    const int tid = threadIdx.x;
    const int b   = blockIdx.x >> 4;
    const int p0  = (blockIdx.x & 15) * TPOS;

    // --- Stage raw x0 -> slot3, x1 -> slot4
    {
        const float4* gx0 = reinterpret_cast<const float4*>(x0 + b * 65536 + p0);
        const float4* gx1 = reinterpret_cast<const float4*>(x1 + b * 65536 + p0);
        float4* s3 = reinterpret_cast<float4*>(st + 3 * SLOT);
        float4* s4 = reinterpret_cast<float4*>(st + 4 * SLOT);
        #pragma unroll
        for (int j = 0; j < 8; ++j) {
            int id = tid + j * NTHREADS;     // 0..1023 float4s = [64 c][16 q]
            int c = id >> 4;
            int q = id & 15;
            s3[id] = gx0[c * 256 + q];
            s4[id] = gx1[c * 256 + q];
        }
    }

    // --- Weight prologue: w0 -> buf0 ; w1 prefetched into regs
    float4 wr[8];
    {
        const float4* s0 = reinterpret_cast<const float4*>(g_wsp);
        #pragma unroll
        for (int j = 0; j < 8; ++j) wr[j] = s0[tid + j * NTHREADS];
        float4* d0 = reinterpret_cast<float4*>(wb);
        #pragma unroll
        for (int j = 0; j < 8; ++j) d0[tid + j * NTHREADS] = wr[j];
        const float4* s1 = reinterpret_cast<const float4*>(g_wsp + 4096);
        #pragma unroll
        for (int j = 0; j < 8; ++j) wr[j] = s1[tid + j * NTHREADS];
    }
    __syncthreads();

    // --- Thread tile: 8 o x 4 p
    const int og = tid >> 4;          // 0..7
    const int pg = tid & 15;          // 0..15
    const int o0 = og * 8;
    const int pA = pg * 4;

    unsigned long long A[8][2];       // [o][pos-pair]

    #pragma unroll 1
    for (int g = 0; g < NG; ++g) {
        const int s_in = c_in[g];
        if (c_start[g]) {
            #pragma unroll
            for (int i = 0; i < 8; ++i) { A[i][0] = 0ull; A[i][1] = 0ull; }
        }
        // --- GEMM: A += W[g] * state[s_in]
        {
            const float* xp = st + s_in * SLOT + pA;
            const float* wp = wb + (g & 1) * 4096 + o0;
            #pragma unroll 8
            for (int c = 0; c < 64; ++c) {
                ulonglong2 xa = *reinterpret_cast<const ulonglong2*>(xp);
                float4 w0 = *reinterpret_cast<const float4*>(wp);
                float4 w1 = *reinterpret_cast<const float4*>(wp + 4);
                unsigned long long s0 = splat2(w0.x), s1 = splat2(w0.y);
                unsigned long long s2 = splat2(w0.z), s3 = splat2(w0.w);
                unsigned long long s4 = splat2(w1.x), s5 = splat2(w1.y);
                unsigned long long s6 = splat2(w1.z), s7 = splat2(w1.w);
                // grouped by x operand (slot-b reuse across consecutive FMAs)
                ffma2(A[0][0], s0, xa.x); ffma2(A[1][0], s1, xa.x);
                ffma2(A[2][0], s2, xa.x); ffma2(A[3][0], s3, xa.x);
                ffma2(A[4][0], s4, xa.x); ffma2(A[5][0], s5, xa.x);
                ffma2(A[6][0], s6, xa.x); ffma2(A[7][0], s7, xa.x);
                ffma2(A[0][1], s0, xa.y); ffma2(A[1][1], s1, xa.y);
                ffma2(A[2][1], s2, xa.y); ffma2(A[3][1], s3, xa.y);
                ffma2(A[4][1], s4, xa.y); ffma2(A[5][1], s5, xa.y);
                ffma2(A[6][1], s6, xa.y); ffma2(A[7][1], s7, xa.y);
                xp += TPOS;
                wp += 64;
            }
        }
        // --- State finished
        {
            const int f = c_fins[g];
            if (f >= 0) {
                if (f >= 2) {   // node raw -> global
                    const int node = (f == 5) ? 3 : (f - 2);
                    float* gp = out + b * 262144 + node * 65536 + p0 + pA;
                    #pragma unroll
                    for (int oo = 0; oo < 8; ++oo) {
                        float2 a0 = u2f2(A[oo][0]), a1 = u2f2(A[oo][1]);
                        *reinterpret_cast<float4*>(gp + (o0 + oo) * 1024) =
                            make_float4(a0.x, a0.y, a1.x, a1.y);
                    }
                }
                if (f <= 4) {   // relu'd -> smem slot f
                    float* sd = st + f * SLOT + pA;
                    #pragma unroll
                    for (int oo = 0; oo < 8; ++oo) {
                        float2 a0 = u2f2(A[oo][0]), a1 = u2f2(A[oo][1]);
                        *reinterpret_cast<float4*>(sd + (o0 + oo) * TPOS) =
                            make_float4(fmaxf(a0.x, 0.f), fmaxf(a0.y, 0.f),
                                        fmaxf(a1.x, 0.f), fmaxf(a1.y, 0.f));
                    }
                }
            }
        }
        // --- Weight staging: STS w[g+1] (in regs), prefetch LDG w[g+2]
        if (g + 1 < NG) {
            float4* d = reinterpret_cast<float4*>(wb + ((g + 1) & 1) * 4096);
            #pragma unroll
            for (int j = 0; j < 8; ++j) d[tid + j * NTHREADS] = wr[j];
        }
        if (g + 2 < NG) {
            const float4* s =
                reinterpret_cast<const float4*>(g_wsp + (g + 2) * 4096);
            #pragma unroll
            for (int j = 0; j < 8; ++j) wr[j] = s[tid + j * NTHREADS];
        }
        __syncthreads();
    }
}

extern "C" void kernel_launch(void* const* d_in, const int* in_sizes, int n_in,
                              void* d_out, int out_size) {
    const float* x0    = (const float*)d_in[0];
    const float* x1    = (const float*)d_in[1];
    const float* Wpre  = (const float*)d_in[2];
    const float* Wedge = (const float*)d_in[3];
    float* out = (float*)d_out;

    prep_weights_kernel<<<256, 256>>>(Wpre, Wedge);

    cudaFuncSetAttribute(dag_kernel,
                         cudaFuncAttributeMaxDynamicSharedMemorySize,
                         SMEM_BYTES);
    dag_kernel<<<1024, NTHREADS, SMEM_BYTES>>>(x0, x1, out);
}

// round 9
// speedup vs baseline: 1.6835x; 1.6835x over previous
#include <cuda_runtime.h>
#include <cuda_bf16.h>

typedef unsigned int u32;

#define NG 16
#define NTHREADS 256

// smem: 5 A slots (hi 16K || lo 16K, SW128 [pos][128B]) + 2 B buffers
#define ASLOT   32768
#define SM_B    (5 * ASLOT)            // 163840
#define BBUF    16384                  // hi 8K || lo 8K
#define SMEM_BYTES (SM_B + 2 * BBUF)   // 196608

// schedule (R6-validated): slots 0=s0 1=s1 2=n0 3=n1 4=n2; x0->3, x1->4
__constant__ int c_in[NG]  = {3,4, 0,1, 0,1,2, 0,1,2,3, 0,1,2,3,4};
__constant__ int c_st[NG]  = {1,1, 1,0, 1,0,0, 1,0,0,0, 1,0,0,0,0};
__constant__ int c_fin[NG] = {0,1, -1,2, -1,-1,3, -1,-1,-1,4, -1,-1,-1,-1,5};

// [g]: pre-swizzled SW128 B-tile image (rows=o, 128B), hi 8KB || lo 8KB
__device__ __align__(16) unsigned char g_bsp[NG * 16384];

__device__ __forceinline__ u32 sw128(u32 o) { return o ^ ((o >> 3) & 0x70); }

// split 8 fp32 -> bf16 hi/lo packed uint4 (even element in low half)
__device__ __forceinline__ void split8(const float* f, uint4& hv, uint4& lv) {
    u32 h[4], l[4];
#pragma unroll
    for (int j = 0; j < 4; ++j) {
        float a = f[2*j], b = f[2*j+1];
        u32 hp;
        asm("cvt.rn.bf16x2.f32 %0, %1, %2;" : "=r"(hp) : "f"(b), "f"(a));
        float ra = a - __uint_as_float(hp << 16);
        float rb = b - __uint_as_float(hp & 0xFFFF0000u);
        u32 lp;
        asm("cvt.rn.bf16x2.f32 %0, %1, %2;" : "=r"(lp) : "f"(rb), "f"(ra));
        h[j] = hp; l[j] = lp;
    }
    hv = make_uint4(h[0], h[1], h[2], h[3]);
    lv = make_uint4(l[0], l[1], l[2], l[3]);
}

// pack one fp32 pair -> bf16x2 hi word + lo word
__device__ __forceinline__ void split2(float v0, float v1, u32& hp, u32& lp) {
    asm("cvt.rn.bf16x2.f32 %0, %1, %2;" : "=r"(hp) : "f"(v1), "f"(v0));
    float r0 = v0 - __uint_as_float(hp << 16);
    float r1 = v1 - __uint_as_float(hp & 0xFFFF0000u);
    asm("cvt.rn.bf16x2.f32 %0, %1, %2;" : "=r"(lp) : "f"(r1), "f"(r0));
}

__global__ void prep_weights_kernel(const float* __restrict__ Wpre,
                                    const float* __restrict__ Wedge) {
    int idx = blockIdx.x * blockDim.x + threadIdx.x;   // g*64 + o
    if (idx >= NG * 64) return;
    int g = idx >> 6, o = idx & 63;
    const float* wrow = (g < 2 ? Wpre + g * 4096 : Wedge + (g - 2) * 4096)
                        + o * 64;
    unsigned char* base = g_bsp + g * 16384;
#pragma unroll
    for (int i = 0; i < 8; ++i) {
        float f[8];
#pragma unroll
        for (int j = 0; j < 8; ++j) f[j] = wrow[i * 8 + j];
        uint4 hv, lv;
        split8(f, hv, lv);
        u32 off = sw128((u32)(o * 128 + i * 16));
        *reinterpret_cast<uint4*>(base + off) = hv;
        *reinterpret_cast<uint4*>(base + 8192 + off) = lv;
    }
}

__device__ __forceinline__ void ldm_x4(u32 a, u32* r) {
    asm volatile("ldmatrix.sync.aligned.m8n8.x4.shared.b16 {%0,%1,%2,%3}, [%4];"
        : "=r"(r[0]), "=r"(r[1]), "=r"(r[2]), "=r"(r[3]) : "r"(a));
}
__device__ __forceinline__ void ldm_x2(u32 a, u32* r) {
    asm volatile("ldmatrix.sync.aligned.m8n8.x2.shared.b16 {%0,%1}, [%2];"
        : "=r"(r[0]), "=r"(r[1]) : "r"(a));
}
__device__ __forceinline__ void mma16816(float* d, const u32* a, const u32* b) {
    asm volatile(
        "mma.sync.aligned.m16n8k16.row.col.f32.bf16.bf16.f32 "
        "{%0,%1,%2,%3},{%4,%5,%6,%7},{%8,%9},{%0,%1,%2,%3};"
        : "+f"(d[0]), "+f"(d[1]), "+f"(d[2]), "+f"(d[3])
        : "r"(a[0]), "r"(a[1]), "r"(a[2]), "r"(a[3]), "r"(b[0]), "r"(b[1]));
}

__global__ void __launch_bounds__(NTHREADS, 1)
dag_kernel(const float* __restrict__ x0, const float* __restrict__ x1,
           float* __restrict__ out) {
    extern __shared__ __align__(1024) unsigned char sm[];
    u32 smb;
    asm("{.reg .u64 t; cvta.to.shared.u64 t, %1; cvt.u32.u64 %0, t;}"
        : "=r"(smb) : "l"(sm));

    const int tid  = threadIdx.x;
    const int lane = tid & 31;
    const int wid  = tid >> 5;
    const int b    = blockIdx.x >> 3;
    const int p0   = (blockIdx.x & 7) * 128;

    // --- stage x0 -> slot3, x1 -> slot4 (thread = one position row)
    {
        const int half = tid >> 7;              // 0: x0, 1: x1
        const int p    = tid & 127;
        const float* gx = (half ? x1 : x0) + b * 65536 + p0 + p;
        unsigned char* slot = sm + (3 + half) * ASLOT;
        const u32 xm = (u32)((p & 7) << 4);
#pragma unroll
        for (int i = 0; i < 8; ++i) {
            float f[8];
#pragma unroll
            for (int j = 0; j < 8; ++j) f[j] = gx[(i * 8 + j) * 1024];
            uint4 hv, lv;
            split8(f, hv, lv);
            u32 off = (u32)(p * 128) + (((u32)(i * 16)) ^ xm);
            *reinterpret_cast<uint4*>(slot + off) = hv;
            *reinterpret_cast<uint4*>(slot + 16384 + off) = lv;
        }
    }

    // --- B prologue: B0 -> buf0; B1 prefetched
    uint4 brE[4], brO[4];
    {
        const uint4* s0 = reinterpret_cast<const uint4*>(g_bsp);
        uint4 t0[4];
#pragma unroll
        for (int j = 0; j < 4; ++j) t0[j] = s0[tid + j * 256];
        uint4* d0 = reinterpret_cast<uint4*>(sm + SM_B);
#pragma unroll
        for (int j = 0; j < 4; ++j) d0[tid + j * 256] = t0[j];
        const uint4* s1 = reinterpret_cast<const uint4*>(g_bsp + 16384);
#pragma unroll
        for (int j = 0; j < 4; ++j) brO[j] = s1[tid + j * 256];
    }
    __syncthreads();

    // --- warp tile: (wm,wn) of 4x2, warp covers 32 pos x 32 out
    const int m0 = (wid & 3) * 32;
    const int n0 = (wid >> 2) * 32;
    const int arow  = m0 + (lane & 15);          // +mt*16
    const int acolb = (lane >> 4) * 16;          // +kk*32 (bytes)
    const int brow  = n0 + (lane & 7);           // +nt*8
    const int bcolb = ((lane >> 3) & 1) * 16;    // +kk*32 (bytes)
    const u32 axm = (u32)((lane & 7) << 4);      // sw128 XOR masks (const/thread)
    const int prow = lane >> 2;
    const int pcol = (lane & 3) * 2;
    const u32 pxm = (u32)(prow << 4);

    float d[2][4][4];

#pragma unroll 1
    for (int g = 0; g < NG; ++g) {
        if (c_st[g]) {
#pragma unroll
            for (int mt = 0; mt < 2; ++mt)
#pragma unroll
                for (int nt = 0; nt < 4; ++nt)
#pragma unroll
                    for (int e = 0; e < 4; ++e) d[mt][nt][e] = 0.f;
        }
        // --- GEMM: d += state[s_in] x W[g]^T  (hi*hi + hi*lo + lo*hi)
        {
            const u32 ah_b = smb + c_in[g] * ASLOT;
            const u32 al_b = ah_b + 16384;
            const u32 bh_b = smb + SM_B + (g & 1) * BBUF;
            const u32 bl_b = bh_b + 8192;
#pragma unroll
            for (int kk = 0; kk < 4; ++kk) {
                const u32 akb = ((u32)(acolb + kk * 32)) ^ axm;
                const u32 bkb = ((u32)(bcolb + kk * 32)) ^ axm;
                u32 ah[2][4], al[2][4], bh[4][2], bl[4][2];
#pragma unroll
                for (int mt = 0; mt < 2; ++mt) {
                    u32 ro = (u32)((arow + mt * 16) * 128) + akb;
                    ldm_x4(ah_b + ro, ah[mt]);
                    ldm_x4(al_b + ro, al[mt]);
                }
#pragma unroll
                for (int nt = 0; nt < 4; ++nt) {
                    u32 ro = (u32)((brow + nt * 8) * 128) + bkb;
                    ldm_x2(bh_b + ro, bh[nt]);
                    ldm_x2(bl_b + ro, bl[nt]);
                }
#pragma unroll
                for (int mt = 0; mt < 2; ++mt)
#pragma unroll
                    for (int nt = 0; nt < 4; ++nt) {
                        mma16816(d[mt][nt], ah[mt], bh[nt]);
                        mma16816(d[mt][nt], ah[mt], bl[nt]);
                        mma16816(d[mt][nt], al[mt], bh[nt]);
                    }
            }
        }
        // --- state finished: raw -> global (nodes), relu+split -> A slot
        {
            const int f = c_fin[g];
            if (f >= 0) {
                if (f >= 2) {
                    const int node = (f == 5) ? 3 : (f - 2);
                    float* gp = out + b * 262144 + node * 65536 + p0;
#pragma unroll
                    for (int mt = 0; mt < 2; ++mt)
#pragma unroll
                        for (int nt = 0; nt < 4; ++nt) {
                            const int o = n0 + nt * 8 + pcol;
                            const int p = m0 + mt * 16 + prow;
                            gp[o * 1024 + p]           = d[mt][nt][0];
                            gp[(o + 1) * 1024 + p]     = d[mt][nt][1];
                            gp[o * 1024 + p + 8]       = d[mt][nt][2];
                            gp[(o + 1) * 1024 + p + 8] = d[mt][nt][3];
                        }
                }
                if (f <= 4) {
                    unsigned char* sd = sm + f * ASLOT;
#pragma unroll
                    for (int mt = 0; mt < 2; ++mt)
#pragma unroll
                        for (int nt = 0; nt < 4; ++nt) {
                            const int p = m0 + mt * 16 + prow;
                            const int c = n0 + nt * 8 + pcol;
                            const u32 cb = ((u32)(c * 2)) ^ pxm;
                            u32 hp, lp;
                            split2(fmaxf(d[mt][nt][0], 0.f),
                                   fmaxf(d[mt][nt][1], 0.f), hp, lp);
                            u32 off = (u32)(p * 128) + cb;
                            *reinterpret_cast<u32*>(sd + off) = hp;
                            *reinterpret_cast<u32*>(sd + 16384 + off) = lp;
                            split2(fmaxf(d[mt][nt][2], 0.f),
                                   fmaxf(d[mt][nt][3], 0.f), hp, lp);
                            off = (u32)((p + 8) * 128) + cb;
                            *reinterpret_cast<u32*>(sd + off) = hp;
                            *reinterpret_cast<u32*>(sd + 16384 + off) = lp;
                        }
                }
            }
        }
        // --- B staging: prefetch B[g+2], STS B[g+1] into other buffer
        if (g + 2 < NG) {
            const uint4* s = reinterpret_cast<const uint4*>(g_bsp + (g + 2) * 16384);
            if (g & 1) {
#pragma unroll
                for (int j = 0; j < 4; ++j) brO[j] = s[tid + j * 256];
            } else {
#pragma unroll
                for (int j = 0; j < 4; ++j) brE[j] = s[tid + j * 256];
            }
        }
        if (g + 1 < NG) {
            uint4* dst = reinterpret_cast<uint4*>(sm + SM_B + ((g + 1) & 1) * BBUF);
            if (g & 1) {
#pragma unroll
                for (int j = 0; j < 4; ++j) dst[tid + j * 256] = brE[j];
            } else {
#pragma unroll
                for (int j = 0; j < 4; ++j) dst[tid + j * 256] = brO[j];
            }
        }
        __syncthreads();
    }
}

extern "C" void kernel_launch(void* const* d_in, const int* in_sizes, int n_in,
                              void* d_out, int out_size) {
    const float* x0    = (const float*)d_in[0];
    const float* x1    = (const float*)d_in[1];
    const float* Wpre  = (const float*)d_in[2];
    const float* Wedge = (const float*)d_in[3];
    float* out = (float*)d_out;

    prep_weights_kernel<<<8, 128>>>(Wpre, Wedge);

    cudaFuncSetAttribute(dag_kernel,
                         cudaFuncAttributeMaxDynamicSharedMemorySize,
                         SMEM_BYTES);
    dag_kernel<<<512, NTHREADS, SMEM_BYTES>>>(x0, x1, out);
}

// round 10
// speedup vs baseline: 1.7919x; 1.0644x over previous
#include <cuda_runtime.h>
#include <cuda_bf16.h>

typedef unsigned int u32;

#define NG 16
#define NTHREADS 256

// 64-pos tiles: A slot = 64 rows x 128B, hi 8K || lo 8K
#define ASLOT   16384
#define SM_B    (5 * ASLOT)            // 81920
#define BBUF    16384                  // hi 8K || lo 8K
#define SMEM_BYTES (SM_B + 2 * BBUF)   // 114688 = 112 KB -> 2 blocks/SM

// schedule (validated): slots 0=s0 1=s1 2=n0 3=n1 4=n2; x0->3, x1->4
__constant__ int c_in[NG]  = {3,4, 0,1, 0,1,2, 0,1,2,3, 0,1,2,3,4};
__constant__ int c_st[NG]  = {1,1, 1,0, 1,0,0, 1,0,0,0, 1,0,0,0,0};
__constant__ int c_fin[NG] = {0,1, -1,2, -1,-1,3, -1,-1,-1,4, -1,-1,-1,-1,5};

// [g]: pre-swizzled SW128 B-tile image (rows=o, 128B), hi 8KB || lo 8KB
__device__ __align__(16) unsigned char g_bsp[NG * 16384];

__device__ __forceinline__ u32 sw128(u32 o) { return o ^ ((o >> 3) & 0x70); }

__device__ __forceinline__ void split8(const float* f, uint4& hv, uint4& lv) {
    u32 h[4], l[4];
#pragma unroll
    for (int j = 0; j < 4; ++j) {
        float a = f[2*j], b = f[2*j+1];
        u32 hp;
        asm("cvt.rn.bf16x2.f32 %0, %1, %2;" : "=r"(hp) : "f"(b), "f"(a));
        float ra = a - __uint_as_float(hp << 16);
        float rb = b - __uint_as_float(hp & 0xFFFF0000u);
        u32 lp;
        asm("cvt.rn.bf16x2.f32 %0, %1, %2;" : "=r"(lp) : "f"(rb), "f"(ra));
        h[j] = hp; l[j] = lp;
    }
    hv = make_uint4(h[0], h[1], h[2], h[3]);
    lv = make_uint4(l[0], l[1], l[2], l[3]);
}

__device__ __forceinline__ void split2(float v0, float v1, u32& hp, u32& lp) {
    asm("cvt.rn.bf16x2.f32 %0, %1, %2;" : "=r"(hp) : "f"(v1), "f"(v0));
    float r0 = v0 - __uint_as_float(hp << 16);
    float r1 = v1 - __uint_as_float(hp & 0xFFFF0000u);
    asm("cvt.rn.bf16x2.f32 %0, %1, %2;" : "=r"(lp) : "f"(r1), "f"(r0));
}

__global__ void prep_weights_kernel(const float* __restrict__ Wpre,
                                    const float* __restrict__ Wedge) {
    int idx = blockIdx.x * blockDim.x + threadIdx.x;   // g*64 + o
    if (idx >= NG * 64) return;
    int g = idx >> 6, o = idx & 63;
    const float* wrow = (g < 2 ? Wpre + g * 4096 : Wedge + (g - 2) * 4096)
                        + o * 64;
    unsigned char* base = g_bsp + g * 16384;
#pragma unroll
    for (int i = 0; i < 8; ++i) {
        float f[8];
#pragma unroll
        for (int j = 0; j < 8; ++j) f[j] = wrow[i * 8 + j];
        uint4 hv, lv;
        split8(f, hv, lv);
        u32 off = sw128((u32)(o * 128 + i * 16));
        *reinterpret_cast<uint4*>(base + off) = hv;
        *reinterpret_cast<uint4*>(base + 8192 + off) = lv;
    }
}

__device__ __forceinline__ void ldm_x4(u32 a, u32* r) {
    asm volatile("ldmatrix.sync.aligned.m8n8.x4.shared.b16 {%0,%1,%2,%3}, [%4];"
        : "=r"(r[0]), "=r"(r[1]), "=r"(r[2]), "=r"(r[3]) : "r"(a));
}
__device__ __forceinline__ void ldm_x2(u32 a, u32* r) {
    asm volatile("ldmatrix.sync.aligned.m8n8.x2.shared.b16 {%0,%1}, [%2];"
        : "=r"(r[0]), "=r"(r[1]) : "r"(a));
}
__device__ __forceinline__ void mma16816(float* d, const u32* a, const u32* b) {
    asm volatile(
        "mma.sync.aligned.m16n8k16.row.col.f32.bf16.bf16.f32 "
        "{%0,%1,%2,%3},{%4,%5,%6,%7},{%8,%9},{%0,%1,%2,%3};"
        : "+f"(d[0]), "+f"(d[1]), "+f"(d[2]), "+f"(d[3])
        : "r"(a[0]), "r"(a[1]), "r"(a[2]), "r"(a[3]), "r"(b[0]), "r"(b[1]));
}

__global__ void __launch_bounds__(NTHREADS, 2)
dag_kernel(const float* __restrict__ x0, const float* __restrict__ x1,
           float* __restrict__ out) {
    extern __shared__ __align__(1024) unsigned char sm[];
    u32 smb;
    asm("{.reg .u64 t; cvta.to.shared.u64 t, %1; cvt.u32.u64 %0, t;}"
        : "=r"(smb) : "l"(sm));

    const int tid  = threadIdx.x;
    const int lane = tid & 31;
    const int wid  = tid >> 5;
    const int b    = blockIdx.x >> 4;
    const int p0   = (blockIdx.x & 15) * 64;

    // --- stage x0 -> slot3, x1 -> slot4 (2 threads per position row)
    {
        const int half = tid >> 7;                 // 0: x0, 1: x1
        const int r    = tid & 127;
        const int p    = r >> 1;                   // 0..63
        const int ci   = r & 1;                    // channel half
        const float* gx = (half ? x1 : x0) + b * 65536 + p0 + p;
        unsigned char* slot = sm + (3 + half) * ASLOT;
        const u32 xm = (u32)((p & 7) << 4);
#pragma unroll
        for (int i = 0; i < 4; ++i) {
            const int ii = ci * 4 + i;
            float f[8];
#pragma unroll
            for (int j = 0; j < 8; ++j) f[j] = gx[(ii * 8 + j) * 1024];
            uint4 hv, lv;
            split8(f, hv, lv);
            u32 off = (u32)(p * 128) + (((u32)(ii * 16)) ^ xm);
            *reinterpret_cast<uint4*>(slot + off) = hv;
            *reinterpret_cast<uint4*>(slot + 8192 + off) = lv;
        }
    }

    // --- B prologue: B0 -> buf0; B1 prefetched
    uint4 brE[4], brO[4];
    {
        const uint4* s0 = reinterpret_cast<const uint4*>(g_bsp);
        uint4 t0[4];
#pragma unroll
        for (int j = 0; j < 4; ++j) t0[j] = s0[tid + j * 256];
        uint4* d0 = reinterpret_cast<uint4*>(sm + SM_B);
#pragma unroll
        for (int j = 0; j < 4; ++j) d0[tid + j * 256] = t0[j];
        const uint4* s1 = reinterpret_cast<const uint4*>(g_bsp + 16384);
#pragma unroll
        for (int j = 0; j < 4; ++j) brO[j] = s1[tid + j * 256];
    }
    __syncthreads();

    // --- warp tile: 2x4 warp grid; warp = 32 pos x 16 out
    const int m0 = (wid & 1) * 32;
    const int n0 = (wid >> 1) * 16;
    const int arow  = m0 + (lane & 15);            // +mt*16
    const int acolb = (lane >> 4) * 16;            // +kk*32 (bytes)
    const int brow  = n0 + (lane & 7);             // +nt*8
    const int bcolb = ((lane >> 3) & 1) * 16;
    const u32 axm = (u32)((lane & 7) << 4);
    const int prow = lane >> 2;
    const int pcol = (lane & 3) * 2;
    const u32 pxm = (u32)(prow << 4);

    float d[2][2][4];

#pragma unroll 1
    for (int g = 0; g < NG; ++g) {
        if (c_st[g]) {
#pragma unroll
            for (int mt = 0; mt < 2; ++mt)
#pragma unroll
                for (int nt = 0; nt < 2; ++nt)
#pragma unroll
                    for (int e = 0; e < 4; ++e) d[mt][nt][e] = 0.f;
        }
        // --- GEMM: d += state[s_in] x W[g]^T  (hi*hi + hi*lo + lo*hi)
        {
            const u32 ah_b = smb + c_in[g] * ASLOT;
            const u32 al_b = ah_b + 8192;
            const u32 bh_b = smb + SM_B + (g & 1) * BBUF;
            const u32 bl_b = bh_b + 8192;
#pragma unroll
            for (int kk = 0; kk < 4; ++kk) {
                const u32 akb = ((u32)(acolb + kk * 32)) ^ axm;
                const u32 bkb = ((u32)(bcolb + kk * 32)) ^ axm;
                u32 ah[2][4], al[2][4], bh[2][2], bl[2][2];
#pragma unroll
                for (int mt = 0; mt < 2; ++mt) {
                    u32 ro = (u32)((arow + mt * 16) * 128) + akb;
                    ldm_x4(ah_b + ro, ah[mt]);
                    ldm_x4(al_b + ro, al[mt]);
                }
#pragma unroll
                for (int nt = 0; nt < 2; ++nt) {
                    u32 ro = (u32)((brow + nt * 8) * 128) + bkb;
                    ldm_x2(bh_b + ro, bh[nt]);
                    ldm_x2(bl_b + ro, bl[nt]);
                }
#pragma unroll
                for (int mt = 0; mt < 2; ++mt)
#pragma unroll
                    for (int nt = 0; nt < 2; ++nt) {
                        mma16816(d[mt][nt], ah[mt], bh[nt]);
                        mma16816(d[mt][nt], ah[mt], bl[nt]);
                        mma16816(d[mt][nt], al[mt], bh[nt]);
                    }
            }
        }
        // --- state finished: raw -> global (nodes), relu+split -> A slot
        {
            const int f = c_fin[g];
            if (f >= 0) {
                if (f >= 2) {
                    const int node = (f == 5) ? 3 : (f - 2);
                    float* gp = out + b * 262144 + node * 65536 + p0;
#pragma unroll
                    for (int mt = 0; mt < 2; ++mt)
#pragma unroll
                        for (int nt = 0; nt < 2; ++nt) {
                            const int o = n0 + nt * 8 + pcol;
                            const int p = m0 + mt * 16 + prow;
                            gp[o * 1024 + p]           = d[mt][nt][0];
                            gp[(o + 1) * 1024 + p]     = d[mt][nt][1];
                            gp[o * 1024 + p + 8]       = d[mt][nt][2];
                            gp[(o + 1) * 1024 + p + 8] = d[mt][nt][3];
                        }
                }
                if (f <= 4) {
                    unsigned char* sd = sm + f * ASLOT;
#pragma unroll
                    for (int mt = 0; mt < 2; ++mt)
#pragma unroll
                        for (int nt = 0; nt < 2; ++nt) {
                            const int p = m0 + mt * 16 + prow;
                            const int c = n0 + nt * 8 + pcol;
                            const u32 cb = ((u32)(c * 2)) ^ pxm;
                            u32 hp, lp;
                            split2(fmaxf(d[mt][nt][0], 0.f),
                                   fmaxf(d[mt][nt][1], 0.f), hp, lp);
                            u32 off = (u32)(p * 128) + cb;
                            *reinterpret_cast<u32*>(sd + off) = hp;
                            *reinterpret_cast<u32*>(sd + 8192 + off) = lp;
                            split2(fmaxf(d[mt][nt][2], 0.f),
                                   fmaxf(d[mt][nt][3], 0.f), hp, lp);
                            off = (u32)((p + 8) * 128) + cb;
                            *reinterpret_cast<u32*>(sd + off) = hp;
                            *reinterpret_cast<u32*>(sd + 8192 + off) = lp;
                        }
                }
            }
        }
        // --- B staging: prefetch B[g+2], STS B[g+1] into other buffer
        if (g + 2 < NG) {
            const uint4* s = reinterpret_cast<const uint4*>(g_bsp + (g + 2) * 16384);
            if (g & 1) {
#pragma unroll
                for (int j = 0; j < 4; ++j) brO[j] = s[tid + j * 256];
            } else {
#pragma unroll
                for (int j = 0; j < 4; ++j) brE[j] = s[tid + j * 256];
            }
        }
        if (g + 1 < NG) {
            uint4* dst = reinterpret_cast<uint4*>(sm + SM_B + ((g + 1) & 1) * BBUF);
            if (g & 1) {
#pragma unroll
                for (int j = 0; j < 4; ++j) dst[tid + j * 256] = brE[j];
            } else {
#pragma unroll
                for (int j = 0; j < 4; ++j) dst[tid + j * 256] = brO[j];
            }
        }
        __syncthreads();
    }
}

extern "C" void kernel_launch(void* const* d_in, const int* in_sizes, int n_in,
                              void* d_out, int out_size) {
    const float* x0    = (const float*)d_in[0];
    const float* x1    = (const float*)d_in[1];
    const float* Wpre  = (const float*)d_in[2];
    const float* Wedge = (const float*)d_in[3];
    float* out = (float*)d_out;

    prep_weights_kernel<<<8, 128>>>(Wpre, Wedge);

    cudaFuncSetAttribute(dag_kernel,
                         cudaFuncAttributeMaxDynamicSharedMemorySize,
                         SMEM_BYTES);
    dag_kernel<<<1024, NTHREADS, SMEM_BYTES>>>(x0, x1, out);
}

// round 11
// speedup vs baseline: 1.8359x; 1.0245x over previous
#include <cuda_runtime.h>
#include <cuda_bf16.h>

typedef unsigned int u32;

#define NG 16
#define NTHREADS 256

// 64-pos tiles: A slot = 64 rows x 128B, hi 8K || lo 8K
#define ASLOT   16384
#define SM_B    (5 * ASLOT)            // 81920
#define BBUF    16384                  // hi 8K || lo 8K
#define SMEM_BYTES (SM_B + 2 * BBUF)   // 114688 -> 2 blocks/SM

// schedule (validated): slots 0=s0 1=s1 2=n0 3=n1 4=n2; x0->3, x1->4
__constant__ int c_in[NG]  = {3,4, 0,1, 0,1,2, 0,1,2,3, 0,1,2,3,4};
__constant__ int c_st[NG]  = {1,1, 1,0, 1,0,0, 1,0,0,0, 1,0,0,0,0};
__constant__ int c_fin[NG] = {0,1, -1,2, -1,-1,3, -1,-1,-1,4, -1,-1,-1,-1,5};

// [g]: pre-swizzled SW128 B-tile image (rows=o, 128B), hi 8KB || lo 8KB
__device__ __align__(16) unsigned char g_bsp[NG * 16384];

__device__ __forceinline__ u32 sw128(u32 o) { return o ^ ((o >> 3) & 0x70); }

__device__ __forceinline__ void split8(const float* f, uint4& hv, uint4& lv) {
    u32 h[4], l[4];
#pragma unroll
    for (int j = 0; j < 4; ++j) {
        float a = f[2*j], b = f[2*j+1];
        u32 hp;
        asm("cvt.rn.bf16x2.f32 %0, %1, %2;" : "=r"(hp) : "f"(b), "f"(a));
        float ra = a - __uint_as_float(hp << 16);
        float rb = b - __uint_as_float(hp & 0xFFFF0000u);
        u32 lp;
        asm("cvt.rn.bf16x2.f32 %0, %1, %2;" : "=r"(lp) : "f"(rb), "f"(ra));
        h[j] = hp; l[j] = lp;
    }
    hv = make_uint4(h[0], h[1], h[2], h[3]);
    lv = make_uint4(l[0], l[1], l[2], l[3]);
}

__device__ __forceinline__ void split2(float v0, float v1, u32& hp, u32& lp) {
    asm("cvt.rn.bf16x2.f32 %0, %1, %2;" : "=r"(hp) : "f"(v1), "f"(v0));
    float r0 = v0 - __uint_as_float(hp << 16);
    float r1 = v1 - __uint_as_float(hp & 0xFFFF0000u);
    asm("cvt.rn.bf16x2.f32 %0, %1, %2;" : "=r"(lp) : "f"(r1), "f"(r0));
}

__global__ void prep_weights_kernel(const float* __restrict__ Wpre,
                                    const float* __restrict__ Wedge) {
    int idx = blockIdx.x * blockDim.x + threadIdx.x;   // g*64 + o
    if (idx >= NG * 64) return;
    int g = idx >> 6, o = idx & 63;
    const float* wrow = (g < 2 ? Wpre + g * 4096 : Wedge + (g - 2) * 4096)
                        + o * 64;
    unsigned char* base = g_bsp + g * 16384;
#pragma unroll
    for (int i = 0; i < 8; ++i) {
        float f[8];
#pragma unroll
        for (int j = 0; j < 8; ++j) f[j] = wrow[i * 8 + j];
        uint4 hv, lv;
        split8(f, hv, lv);
        u32 off = sw128((u32)(o * 128 + i * 16));
        *reinterpret_cast<uint4*>(base + off) = hv;
        *reinterpret_cast<uint4*>(base + 8192 + off) = lv;
    }
}

__device__ __forceinline__ void ldm_x4(u32 a, u32* r) {
    asm volatile("ldmatrix.sync.aligned.m8n8.x4.shared.b16 {%0,%1,%2,%3}, [%4];"
        : "=r"(r[0]), "=r"(r[1]), "=r"(r[2]), "=r"(r[3]) : "r"(a));
}
__device__ __forceinline__ void mma16816(float* d, const u32* a, const u32* b) {
    asm volatile(
        "mma.sync.aligned.m16n8k16.row.col.f32.bf16.bf16.f32 "
        "{%0,%1,%2,%3},{%4,%5,%6,%7},{%8,%9},{%0,%1,%2,%3};"
        : "+f"(d[0]), "+f"(d[1]), "+f"(d[2]), "+f"(d[3])
        : "r"(a[0]), "r"(a[1]), "r"(a[2]), "r"(a[3]), "r"(b[0]), "r"(b[1]));
}

__global__ void __launch_bounds__(NTHREADS, 2)
dag_kernel(const float* __restrict__ x0, const float* __restrict__ x1,
           float* __restrict__ out) {
    extern __shared__ __align__(1024) unsigned char sm[];
    u32 smb;
    asm("{.reg .u64 t; cvta.to.shared.u64 t, %1; cvt.u32.u64 %0, t;}"
        : "=r"(smb) : "l"(sm));

    const int tid  = threadIdx.x;
    const int lane = tid & 31;
    const int wid  = tid >> 5;
    const int b    = blockIdx.x >> 4;
    const int p0   = (blockIdx.x & 15) * 64;

    // --- stage x0 -> slot3, x1 -> slot4 (2 threads per position row)
    {
        const int half = tid >> 7;
        const int r    = tid & 127;
        const int p    = r >> 1;
        const int ci   = r & 1;
        const float* gx = (half ? x1 : x0) + b * 65536 + p0 + p;
        unsigned char* slot = sm + (3 + half) * ASLOT;
        const u32 xm = (u32)((p & 7) << 4);
#pragma unroll
        for (int i = 0; i < 4; ++i) {
            const int ii = ci * 4 + i;
            float f[8];
#pragma unroll
            for (int j = 0; j < 8; ++j) f[j] = gx[(ii * 8 + j) * 1024];
            uint4 hv, lv;
            split8(f, hv, lv);
            u32 off = (u32)(p * 128) + (((u32)(ii * 16)) ^ xm);
            *reinterpret_cast<uint4*>(slot + off) = hv;
            *reinterpret_cast<uint4*>(slot + 8192 + off) = lv;
        }
    }

    // --- B prologue: B0 -> buf0; B1 prefetched into br
    uint4 br[4];
    {
        const uint4* s0 = reinterpret_cast<const uint4*>(g_bsp);
        uint4 t0[4];
#pragma unroll
        for (int j = 0; j < 4; ++j) t0[j] = s0[tid + j * 256];
        uint4* d0 = reinterpret_cast<uint4*>(sm + SM_B);
#pragma unroll
        for (int j = 0; j < 4; ++j) d0[tid + j * 256] = t0[j];
        const uint4* s1 = reinterpret_cast<const uint4*>(g_bsp + 16384);
#pragma unroll
        for (int j = 0; j < 4; ++j) br[j] = s1[tid + j * 256];
    }
    __syncthreads();

    // --- warp mapping: 2m x 2n x 2k; warp = 32 pos x 32 out, half K
    const int kh = wid >> 2;
    const int m0 = (wid & 1) * 32;
    const int n0 = ((wid >> 1) & 1) * 32;
    const int arow  = m0 + (lane & 15);
    const int acolb = (lane >> 4) * 16;
    const int brow4 = n0 + ((lane >> 4) << 3) + (lane & 7);
    const int bcolb = ((lane >> 3) & 1) * 16;
    const u32 axm = (u32)((lane & 7) << 4);
    const int prow = lane >> 2;
    const int pcol = (lane & 3) * 2;
    const u32 pxm = (u32)(prow << 4);

    float d[2][4][4];

#pragma unroll 1
    for (int g = 0; g < NG; ++g) {
        if (c_st[g]) {
#pragma unroll
            for (int mt = 0; mt < 2; ++mt)
#pragma unroll
                for (int nt = 0; nt < 4; ++nt)
#pragma unroll
                    for (int e = 0; e < 4; ++e) d[mt][nt][e] = 0.f;
        }
        // --- GEMM (k-half): d += A[kh] x B[kh]^T  (3 passes)
        {
            const u32 ah_b = smb + c_in[g] * ASLOT;
            const u32 al_b = ah_b + 8192;
            const u32 bh_b = smb + SM_B + (g & 1) * BBUF;
            const u32 bl_b = bh_b + 8192;
#pragma unroll
            for (int kk = 0; kk < 2; ++kk) {
                const int kc = kh * 2 + kk;
                const u32 akb = ((u32)(acolb + kc * 32)) ^ axm;
                const u32 bkb = ((u32)(bcolb + kc * 32)) ^ axm;
                u32 ah[2][4], al[2][4], bh[2][4], bl[2][4];
#pragma unroll
                for (int mt = 0; mt < 2; ++mt) {
                    u32 ro = (u32)((arow + mt * 16) * 128) + akb;
                    ldm_x4(ah_b + ro, ah[mt]);
                    ldm_x4(al_b + ro, al[mt]);
                }
#pragma unroll
                for (int nn = 0; nn < 2; ++nn) {
                    u32 ro = (u32)((brow4 + nn * 16) * 128) + bkb;
                    ldm_x4(bh_b + ro, bh[nn]);
                    ldm_x4(bl_b + ro, bl[nn]);
                }
#pragma unroll
                for (int mt = 0; mt < 2; ++mt)
#pragma unroll
                    for (int nt = 0; nt < 4; ++nt) {
                        const u32* bhf = &bh[nt >> 1][(nt & 1) * 2];
                        const u32* blf = &bl[nt >> 1][(nt & 1) * 2];
                        mma16816(d[mt][nt], ah[mt], bhf);
                        mma16816(d[mt][nt], ah[mt], blf);
                        mma16816(d[mt][nt], al[mt], bhf);
                    }
            }
        }
        // --- state finished: reduce k-halves, raw -> global, relu -> slot
        {
            const int f = c_fin[g];
            if (f >= 0) {
                unsigned char* scr = (f <= 4) ? (sm + f * ASLOT) : (sm + SM_B);
                __syncthreads();                    // all MMA reads done
                if (kh) {                           // upper K half: dump raw
#pragma unroll
                    for (int mt = 0; mt < 2; ++mt)
#pragma unroll
                        for (int nt = 0; nt < 4; ++nt) {
                            const int p = m0 + mt * 16 + prow;
                            const int o = n0 + nt * 8 + pcol;
                            const u32 cb = ((u32)(o * 4)) ^ ((u32)(prow << 5));
                            *reinterpret_cast<float2*>(scr + p * 256 + cb) =
                                make_float2(d[mt][nt][0], d[mt][nt][1]);
                            *reinterpret_cast<float2*>(scr + (p + 8) * 256 + cb) =
                                make_float2(d[mt][nt][2], d[mt][nt][3]);
                        }
                }
                __syncthreads();
                if (!kh) {                          // lower half: add partials
#pragma unroll
                    for (int mt = 0; mt < 2; ++mt)
#pragma unroll
                        for (int nt = 0; nt < 4; ++nt) {
                            const int p = m0 + mt * 16 + prow;
                            const int o = n0 + nt * 8 + pcol;
                            const u32 cb = ((u32)(o * 4)) ^ ((u32)(prow << 5));
                            float2 u = *reinterpret_cast<const float2*>(
                                           scr + p * 256 + cb);
                            float2 v = *reinterpret_cast<const float2*>(
                                           scr + (p + 8) * 256 + cb);
                            d[mt][nt][0] += u.x; d[mt][nt][1] += u.y;
                            d[mt][nt][2] += v.x; d[mt][nt][3] += v.y;
                        }
                }
                __syncthreads();                    // reads done before reuse
                if (!kh) {
                    if (f >= 2) {
                        const int node = (f == 5) ? 3 : (f - 2);
                        float* gp = out + b * 262144 + node * 65536 + p0;
#pragma unroll
                        for (int mt = 0; mt < 2; ++mt)
#pragma unroll
                            for (int nt = 0; nt < 4; ++nt) {
                                const int o = n0 + nt * 8 + pcol;
                                const int p = m0 + mt * 16 + prow;
                                gp[o * 1024 + p]           = d[mt][nt][0];
                                gp[(o + 1) * 1024 + p]     = d[mt][nt][1];
                                gp[o * 1024 + p + 8]       = d[mt][nt][2];
                                gp[(o + 1) * 1024 + p + 8] = d[mt][nt][3];
                            }
                    }
                    if (f <= 4) {
                        unsigned char* sd = sm + f * ASLOT;
#pragma unroll
                        for (int mt = 0; mt < 2; ++mt)
#pragma unroll
                            for (int nt = 0; nt < 4; ++nt) {
                                const int p = m0 + mt * 16 + prow;
                                const int c = n0 + nt * 8 + pcol;
                                const u32 cb = ((u32)(c * 2)) ^ pxm;
                                u32 hp, lp;
                                split2(fmaxf(d[mt][nt][0], 0.f),
                                       fmaxf(d[mt][nt][1], 0.f), hp, lp);
                                u32 off = (u32)(p * 128) + cb;
                                *reinterpret_cast<u32*>(sd + off) = hp;
                                *reinterpret_cast<u32*>(sd + 8192 + off) = lp;
                                split2(fmaxf(d[mt][nt][2], 0.f),
                                       fmaxf(d[mt][nt][3], 0.f), hp, lp);
                                off = (u32)((p + 8) * 128) + cb;
                                *reinterpret_cast<u32*>(sd + off) = hp;
                                *reinterpret_cast<u32*>(sd + 8192 + off) = lp;
                            }
                    }
                }
            }
        }
        // --- B staging: STS B[g+1] (held in br), then prefetch B[g+2]
        if (g + 1 < NG) {
            uint4* dst = reinterpret_cast<uint4*>(sm + SM_B + ((g + 1) & 1) * BBUF);
#pragma unroll
            for (int j = 0; j < 4; ++j) dst[tid + j * 256] = br[j];
        }
        if (g + 2 < NG) {
            const uint4* s = reinterpret_cast<const uint4*>(g_bsp + (g + 2) * 16384);
#pragma unroll
            for (int j = 0; j < 4; ++j) br[j] = s[tid + j * 256];
        }
        __syncthreads();
    }
}

extern "C" void kernel_launch(void* const* d_in, const int* in_sizes, int n_in,
                              void* d_out, int out_size) {
    const float* x0    = (const float*)d_in[0];
    const float* x1    = (const float*)d_in[1];
    const float* Wpre  = (const float*)d_in[2];
    const float* Wedge = (const float*)d_in[3];
    float* out = (float*)d_out;

    prep_weights_kernel<<<8, 128>>>(Wpre, Wedge);

    cudaFuncSetAttribute(dag_kernel,
                         cudaFuncAttributeMaxDynamicSharedMemorySize,
                         SMEM_BYTES);
    dag_kernel<<<1024, NTHREADS, SMEM_BYTES>>>(x0, x1, out);
}